// round 1
// baseline (speedup 1.0000x reference)
#include <cuda_runtime.h>
#include <math.h>

// Problem constants
#define BB   8
#define TT   512
#define DD   128
#define DLL  16
#define KK   8
#define HPHI 32
#define HTH  32
#define NROWS (BB*TT)   // 4096
#define TS   32
#define EPS2 0.0001f

// Scratch (device globals: no allocation allowed in kernel_launch)
__device__ __align__(16) float g_l[2][NROWS*DLL];     // projected l vectors
__device__ __align__(16) float g_proj[2][NROWS*HTH];  // theta-net row projections
__device__ float g_hn[2][NROWS];                      // |h row|^2
__device__ float g_ln[2][NROWS];                      // |l row|^2

// ---------------------------------------------------------------------------
// Fast, accurate erf (Abramowitz & Stegun 7.1.26, |err| <= 1.5e-7)
// ---------------------------------------------------------------------------
__device__ __forceinline__ float fast_erf(float z) {
    float az = fabsf(z);
    float t  = __fdividef(1.0f, fmaf(0.3275911f, az, 1.0f));
    float p  =             1.061405429f;
    p = fmaf(p, t, -1.453152027f);
    p = fmaf(p, t,  1.421413741f);
    p = fmaf(p, t, -0.284496736f);
    p = fmaf(p, t,  0.254829592f);
    float e = __expf(-az * az);
    float r = fmaf(-p * t, e, 1.0f);
    return copysignf(r, z);
}

__device__ __forceinline__ float geluf(float x) {
    float hx = 0.5f * x;
    return fmaf(hx, fast_erf(x * 0.7071067811865475f), hx);
}

// ---------------------------------------------------------------------------
// Precompute per-row quantities: l = row @ W_l, proj = (row @ W_theta) @ Wcomb,
// and squared norms. grid = (4096, 2), block = 128.
// ---------------------------------------------------------------------------
__global__ void prep_kernel(const float* __restrict__ h,
                            const float* __restrict__ hsrc,
                            const float* __restrict__ W_l,
                            const float* __restrict__ W_theta,
                            const float* __restrict__ wq,
                            const float* __restrict__ ws,
                            const float* __restrict__ wd,
                            const float* __restrict__ b1)
{
    int row  = blockIdx.x;
    int side = blockIdx.y;
    const float* src = (side == 0) ? h : hsrc;

    __shared__ float rs[DD];
    __shared__ float th[KK];
    __shared__ float lr[DLL];

    int tid = threadIdx.x;
    rs[tid] = src[(size_t)row * DD + tid];
    __syncthreads();

    if (tid < DLL) {
        float a = 0.f;
        #pragma unroll 16
        for (int d = 0; d < DD; d++) a = fmaf(rs[d], W_l[d * DLL + tid], a);
        lr[tid] = a;
        g_l[side][row * DLL + tid] = a;
    } else if (tid < DLL + KK) {
        int j = tid - DLL;
        float a = 0.f;
        #pragma unroll 16
        for (int d = 0; d < DD; d++) a = fmaf(rs[d], W_theta[d * KK + j], a);
        th[j] = a;
    }
    __syncthreads();

    if (tid < HTH) {
        float p = (side == 0) ? b1[tid] : 0.f;
        #pragma unroll
        for (int k = 0; k < KK; k++) {
            float w = (side == 0) ? (wq[k * HTH + tid] + wd[k * HTH + tid])
                                  : (ws[k * HTH + tid] - wd[k * HTH + tid]);
            p = fmaf(th[k], w, p);
        }
        g_proj[side][row * HTH + tid] = p;
    } else if (tid == 64) {
        float a = 0.f;
        for (int d = 0; d < DD; d++) a = fmaf(rs[d], rs[d], a);
        g_hn[side][row] = a;
    } else if (tid == 96) {
        float a = 0.f;
        for (int j = 0; j < DLL; j++) a = fmaf(lr[j], lr[j], a);
        g_ln[side][row] = a;
    }
}

// ---------------------------------------------------------------------------
// Per-pair epilogue (noinline to bound I$ footprint: called 4x/thread)
// ---------------------------------------------------------------------------
__device__ __noinline__ float pair_eval(float dh2, float dl2,
        const float* pt, const float* pu,
        const float* cp1w, const float* cp1b, const float* cp2w, const float* cw2,
        float ph2b, float w2b)
{
    float rinv = rsqrtf(dh2 + EPS2);

    // Phi = exp(-softplus(phi-net(dl2)) * dl2)
    float acc = ph2b;
    #pragma unroll 8
    for (int q = 0; q < HPHI; q++)
        acc = fmaf(geluf(fmaf(dl2, cp1w[q], cp1b[q])), cp2w[q], acc);
    float c   = fmaxf(acc, 0.0f) + log1pf(__expf(-fabsf(acc)));
    float Phi = __expf(-c * dl2);

    // Theta = tanh(sum gelu(pt+pu) * w2 + b)
    float acc2 = w2b;
    #pragma unroll 8
    for (int q = 0; q < HTH; q++)
        acc2 = fmaf(geluf(pt[q] + pu[q]), cw2[q], acc2);
    float Theta = tanhf(acc2);

    return -Theta * Phi * rinv;
}

// ---------------------------------------------------------------------------
// Main kernel: 32x32 pair tile per block, 256 threads, 2x2 micro-tile each.
// grid = (T/32, T/32, B)
// ---------------------------------------------------------------------------
__global__ __launch_bounds__(256)
void main_kernel(const float* __restrict__ h, const float* __restrict__ hsrc,
                 const float* __restrict__ phi1_w, const float* __restrict__ phi1_b,
                 const float* __restrict__ phi2_w, const float* __restrict__ phi2_b,
                 const float* __restrict__ w2_w,  const float* __restrict__ w2_b,
                 float* __restrict__ out)
{
    __shared__ float4 sha[TS][33];   // h rows,   132-float stride (conflict-free LDS.128)
    __shared__ float4 shb[TS][33];   // hsrc rows
    __shared__ float4 sla[TS][5];    // l rows,   20-float stride
    __shared__ float4 slb[TS][5];
    __shared__ float  spt[TS][HTH + 1];  // proj rows, 33-float stride
    __shared__ float  spu[TS][HTH + 1];
    __shared__ float  shn[TS], sgn[TS], sln[TS], slsn[TS];
    __shared__ float  cp1w[HPHI], cp1b[HPHI], cp2w[HPHI], cw2[HTH];

    int bz  = blockIdx.z;
    int t0  = blockIdx.y * TS;
    int s0  = blockIdx.x * TS;
    int tid = threadIdx.x;
    int rt  = bz * TT + t0;
    int rs  = bz * TT + s0;

    // --- stage tiles ---
    const float4* hv = (const float4*)(h    + (size_t)rt * DD);
    const float4* gv = (const float4*)(hsrc + (size_t)rs * DD);
    #pragma unroll
    for (int i = 0; i < 4; i++) {
        int idx = tid + i * 256;
        int r = idx >> 5, c2 = idx & 31;
        sha[r][c2] = hv[r * 32 + c2];
        shb[r][c2] = gv[r * 32 + c2];
    }
    if (tid < 128) {
        const float4* lv  = (const float4*)(g_l[0] + rt * DLL);
        const float4* lsv = (const float4*)(g_l[1] + rs * DLL);
        int r = tid >> 2, c2 = tid & 3;
        sla[r][c2] = lv[r * 4 + c2];
        slb[r][c2] = lsv[r * 4 + c2];
    }
    {
        const float* ptg = g_proj[0] + (size_t)rt * HTH;
        const float* pug = g_proj[1] + (size_t)rs * HTH;
        #pragma unroll
        for (int i = 0; i < 4; i++) {
            int idx = tid + i * 256;
            int r = idx >> 5, c2 = idx & 31;
            spt[r][c2] = ptg[r * HTH + c2];
            spu[r][c2] = pug[r * HTH + c2];
        }
    }
    if (tid < TS) {
        shn[tid]  = g_hn[0][rt + tid];
        sgn[tid]  = g_hn[1][rs + tid];
        sln[tid]  = g_ln[0][rt + tid];
        slsn[tid] = g_ln[1][rs + tid];
    } else if (tid >= 64 && tid < 96) {
        int q = tid - 64;
        cp1w[q] = phi1_w[q]; cp1b[q] = phi1_b[q];
        cp2w[q] = phi2_w[q]; cw2[q]  = w2_w[q];
    }
    float ph2b = phi2_b[0];
    float w2b  = w2_b[0];
    __syncthreads();

    int tx = tid & 15, ty = tid >> 4;

    // --- 128-dim dot products (2x2 micro-tile) ---
    float d00 = 0.f, d01 = 0.f, d10 = 0.f, d11 = 0.f;
    #pragma unroll 8
    for (int k = 0; k < 32; k++) {
        float4 a0 = sha[ty][k];
        float4 a1 = sha[ty + 16][k];
        float4 b0 = shb[tx][k];
        float4 b1 = shb[tx + 16][k];
        d00 = fmaf(a0.x, b0.x, d00); d00 = fmaf(a0.y, b0.y, d00);
        d00 = fmaf(a0.z, b0.z, d00); d00 = fmaf(a0.w, b0.w, d00);
        d01 = fmaf(a0.x, b1.x, d01); d01 = fmaf(a0.y, b1.y, d01);
        d01 = fmaf(a0.z, b1.z, d01); d01 = fmaf(a0.w, b1.w, d01);
        d10 = fmaf(a1.x, b0.x, d10); d10 = fmaf(a1.y, b0.y, d10);
        d10 = fmaf(a1.z, b0.z, d10); d10 = fmaf(a1.w, b0.w, d10);
        d11 = fmaf(a1.x, b1.x, d11); d11 = fmaf(a1.y, b1.y, d11);
        d11 = fmaf(a1.z, b1.z, d11); d11 = fmaf(a1.w, b1.w, d11);
    }

    // --- 16-dim l dot products ---
    float e00 = 0.f, e01 = 0.f, e10 = 0.f, e11 = 0.f;
    #pragma unroll
    for (int k = 0; k < 4; k++) {
        float4 a0 = sla[ty][k];
        float4 a1 = sla[ty + 16][k];
        float4 b0 = slb[tx][k];
        float4 b1 = slb[tx + 16][k];
        e00 = fmaf(a0.x, b0.x, e00); e00 = fmaf(a0.y, b0.y, e00);
        e00 = fmaf(a0.z, b0.z, e00); e00 = fmaf(a0.w, b0.w, e00);
        e01 = fmaf(a0.x, b1.x, e01); e01 = fmaf(a0.y, b1.y, e01);
        e01 = fmaf(a0.z, b1.z, e01); e01 = fmaf(a0.w, b1.w, e01);
        e10 = fmaf(a1.x, b0.x, e10); e10 = fmaf(a1.y, b0.y, e10);
        e10 = fmaf(a1.z, b0.z, e10); e10 = fmaf(a1.w, b0.w, e10);
        e11 = fmaf(a1.x, b1.x, e11); e11 = fmaf(a1.y, b1.y, e11);
        e11 = fmaf(a1.z, b1.z, e11); e11 = fmaf(a1.w, b1.w, e11);
    }

    float hn0  = shn[ty],  hn1  = shn[ty + 16];
    float gn0  = sgn[tx],  gn1  = sgn[tx + 16];
    float ln0  = sln[ty],  ln1  = sln[ty + 16];
    float lsn0 = slsn[tx], lsn1 = slsn[tx + 16];

    size_t ob = ((size_t)(bz * TT + t0)) * TT + s0;

    out[ob + (size_t)ty * TT + tx] =
        pair_eval(fmaxf(fmaf(-2.f, d00, hn0 + gn0), 0.f),
                  fmaxf(fmaf(-2.f, e00, ln0 + lsn0), 0.f),
                  spt[ty], spu[tx], cp1w, cp1b, cp2w, cw2, ph2b, w2b);
    out[ob + (size_t)ty * TT + tx + 16] =
        pair_eval(fmaxf(fmaf(-2.f, d01, hn0 + gn1), 0.f),
                  fmaxf(fmaf(-2.f, e01, ln0 + lsn1), 0.f),
                  spt[ty], spu[tx + 16], cp1w, cp1b, cp2w, cw2, ph2b, w2b);
    out[ob + (size_t)(ty + 16) * TT + tx] =
        pair_eval(fmaxf(fmaf(-2.f, d10, hn1 + gn0), 0.f),
                  fmaxf(fmaf(-2.f, e10, ln1 + lsn0), 0.f),
                  spt[ty + 16], spu[tx], cp1w, cp1b, cp2w, cw2, ph2b, w2b);
    out[ob + (size_t)(ty + 16) * TT + tx + 16] =
        pair_eval(fmaxf(fmaf(-2.f, d11, hn1 + gn1), 0.f),
                  fmaxf(fmaf(-2.f, e11, ln1 + lsn1), 0.f),
                  spt[ty + 16], spu[tx + 16], cp1w, cp1b, cp2w, cw2, ph2b, w2b);
}

// ---------------------------------------------------------------------------
extern "C" void kernel_launch(void* const* d_in, const int* in_sizes, int n_in,
                              void* d_out, int out_size)
{
    (void)in_sizes; (void)n_in; (void)out_size;
    const float* h       = (const float*)d_in[0];
    const float* hsrc    = (const float*)d_in[1];
    const float* W_l     = (const float*)d_in[2];
    const float* W_theta = (const float*)d_in[3];
    const float* phi1_w  = (const float*)d_in[4];
    const float* phi1_b  = (const float*)d_in[5];
    const float* phi2_w  = (const float*)d_in[6];
    const float* phi2_b  = (const float*)d_in[7];
    const float* wq      = (const float*)d_in[8];
    const float* ws      = (const float*)d_in[9];
    const float* wd      = (const float*)d_in[10];
    const float* b1      = (const float*)d_in[11];
    const float* w2_w    = (const float*)d_in[12];
    const float* w2_b    = (const float*)d_in[13];
    float* out = (float*)d_out;

    prep_kernel<<<dim3(NROWS, 2), 128>>>(h, hsrc, W_l, W_theta, wq, ws, wd, b1);
    main_kernel<<<dim3(TT / TS, TT / TS, BB), 256>>>(
        h, hsrc, phi1_w, phi1_b, phi2_w, phi2_b, w2_w, w2_b, out);
}

// round 2
// speedup vs baseline: 1.8091x; 1.8091x over previous
#include <cuda_runtime.h>
#include <math.h>

// Problem constants
#define BB   8
#define TT   512
#define DD   128
#define DLL  16
#define KK   8
#define HTH  32
#define NROWS (BB*TT)   // 4096
#define TS   32
#define EPS2 0.0001f

// gelu Taylor coefficients: gelu(x) = 0.5x + C0*x^2 + C1*x^4  (|x| small)
#define C0g  0.3989422804014327f
#define C1g  (-0.06649038006690545f)

// Phi LUT: 2048 entries over dl2 in [0,16), step 1/128
#define LUTN   2048
#define LUTSCL 128.0f

// Scratch (device globals: no allocation allowed in kernel_launch)
__device__ __align__(16) float  g_l[2][NROWS*DLL];    // projected l vectors
__device__ __align__(16) float  g_PQ[2][NROWS*96];    // theta bilinear vectors (P / Q)
__device__ float  g_hn[2][NROWS];                     // |h row|^2
__device__ float  g_ln[2][NROWS];                     // |l row|^2
__device__ float  g_c[2][NROWS];                      // theta per-row constants
__device__ __align__(8) float2 g_lut[LUTN];           // Phi(dl2) LUT: {base, delta}

// ---------------------------------------------------------------------------
// Exact-ish gelu for the LUT builder (perf irrelevant there)
// ---------------------------------------------------------------------------
__device__ __forceinline__ float gelu_exact(float x) {
    return 0.5f * x * (1.0f + erff(x * 0.7071067811865475f));
}

// ---------------------------------------------------------------------------
// Phi LUT builder: Phi(dl2) = exp(-softplus(phi_mlp(dl2)) * dl2)
// grid 8 x 256 -> 2048 entries
// ---------------------------------------------------------------------------
__global__ void lut_kernel(const float* __restrict__ phi1_w,
                           const float* __restrict__ phi1_b,
                           const float* __restrict__ phi2_w,
                           const float* __restrict__ phi2_b)
{
    int idx = blockIdx.x * blockDim.x + threadIdx.x;
    if (idx >= LUTN) return;
    float ph2b = phi2_b[0];
    float phi[2];
    #pragma unroll
    for (int s = 0; s < 2; s++) {
        float dl2 = (float)(idx + s) * (1.0f / LUTSCL);
        float acc = ph2b;
        for (int q = 0; q < 32; q++)
            acc = fmaf(gelu_exact(fmaf(dl2, phi1_w[q], phi1_b[q])), phi2_w[q], acc);
        // stable softplus
        float c = fmaxf(acc, 0.0f) + log1pf(expf(-fabsf(acc)));
        phi[s] = expf(-c * dl2);
    }
    g_lut[idx] = make_float2(phi[0], phi[1] - phi[0]);
}

// ---------------------------------------------------------------------------
// Per-row precompute. grid (NROWS, 2), block 128.
//  side 0: rows of h  (t-side);  side 1: rows of h_src (s-side)
// ---------------------------------------------------------------------------
__global__ void prep_kernel(const float* __restrict__ h,
                            const float* __restrict__ hsrc,
                            const float* __restrict__ W_l,
                            const float* __restrict__ W_theta,
                            const float* __restrict__ wq,
                            const float* __restrict__ ws,
                            const float* __restrict__ wd,
                            const float* __restrict__ b1,
                            const float* __restrict__ w2_w)
{
    int row  = blockIdx.x;
    int side = blockIdx.y;
    const float* src = (side == 0) ? h : hsrc;

    __shared__ float rs[DD];
    __shared__ float th[KK];
    __shared__ float lr[DLL];

    int tid = threadIdx.x;
    rs[tid] = src[(size_t)row * DD + tid];
    __syncthreads();

    if (tid < DLL) {
        float a0 = 0.f, a1 = 0.f, a2 = 0.f, a3 = 0.f;
        #pragma unroll 8
        for (int d = 0; d < DD; d += 4) {
            a0 = fmaf(rs[d    ], W_l[(d    ) * DLL + tid], a0);
            a1 = fmaf(rs[d + 1], W_l[(d + 1) * DLL + tid], a1);
            a2 = fmaf(rs[d + 2], W_l[(d + 2) * DLL + tid], a2);
            a3 = fmaf(rs[d + 3], W_l[(d + 3) * DLL + tid], a3);
        }
        float a = (a0 + a1) + (a2 + a3);
        lr[tid] = a;
        g_l[side][row * DLL + tid] = a;
    } else if (tid < DLL + KK) {
        int j = tid - DLL;
        float a0 = 0.f, a1 = 0.f, a2 = 0.f, a3 = 0.f;
        #pragma unroll 8
        for (int d = 0; d < DD; d += 4) {
            a0 = fmaf(rs[d    ], W_theta[(d    ) * KK + j], a0);
            a1 = fmaf(rs[d + 1], W_theta[(d + 1) * KK + j], a1);
            a2 = fmaf(rs[d + 2], W_theta[(d + 2) * KK + j], a2);
            a3 = fmaf(rs[d + 3], W_theta[(d + 3) * KK + j], a3);
        }
        th[j] = (a0 + a1) + (a2 + a3);
    }
    __syncthreads();

    if (tid < HTH) {
        // projection x = pt[q] (t-side, includes b1) or pu[q] (s-side)
        float x;
        if (side == 0) {
            x = b1[tid];
            #pragma unroll
            for (int k = 0; k < KK; k++)
                x = fmaf(th[k], wq[k * HTH + tid] + wd[k * HTH + tid], x);
        } else {
            x = 0.f;
            #pragma unroll
            for (int k = 0; k < KK; k++)
                x = fmaf(th[k], ws[k * HTH + tid] - wd[k * HTH + tid], x);
        }
        float w2 = w2_w[tid];
        float x2 = x * x;
        float* pq = g_PQ[side] + (size_t)row * 96 + tid * 3;
        if (side == 0) {
            pq[0] = w2 * x * fmaf(4.0f * C1g, x2, 2.0f * C0g);  // 2c0*w2*pt + 4c1*w2*pt^3
            pq[1] = 6.0f * C1g * w2 * x2;                        // 6c1*w2*pt^2
            pq[2] = 4.0f * C1g * w2 * x;                         // 4c1*w2*pt
        } else {
            pq[0] = x;
            pq[1] = x2;
            pq[2] = x2 * x;
        }
        // per-row constant: w2*(0.5x + c0 x^2 + c1 x^4)
        float v = w2 * (fmaf(C1g, x2 * x2, fmaf(C0g, x2, 0.5f * x)));
        #pragma unroll
        for (int o = 16; o > 0; o >>= 1)
            v += __shfl_xor_sync(0xffffffffu, v, o);
        if (tid == 0) g_c[side][row] = v;
    } else if (tid == 32) {
        float a0 = 0.f, a1 = 0.f, a2 = 0.f, a3 = 0.f;
        #pragma unroll 8
        for (int d = 0; d < DD; d += 4) {
            a0 = fmaf(rs[d], rs[d], a0);       a1 = fmaf(rs[d+1], rs[d+1], a1);
            a2 = fmaf(rs[d+2], rs[d+2], a2);   a3 = fmaf(rs[d+3], rs[d+3], a3);
        }
        g_hn[side][row] = (a0 + a1) + (a2 + a3);
    } else if (tid == 33) {
        float a = 0.f;
        #pragma unroll
        for (int j = 0; j < DLL; j++) a = fmaf(lr[j], lr[j], a);
        g_ln[side][row] = a;
    }
}

// ---------------------------------------------------------------------------
// Per-pair epilogue
// ---------------------------------------------------------------------------
__device__ __forceinline__ float pair_out(float d, float e, float p,
                                          float hn, float gn, float ln, float lsn,
                                          float ct, float cs, float w2b)
{
    float dh2 = fmaxf(fmaf(-2.f, d, hn + gn), 0.f) + EPS2;
    float rinv = rsqrtf(dh2);

    float dl2 = fmaxf(fmaf(-2.f, e, ln + lsn), 0.f);
    float t   = fminf(dl2 * LUTSCL, (float)(LUTN - 1));
    int   i   = (int)t;
    float fr  = t - (float)i;
    float2 lv = __ldg(&g_lut[i]);
    float Phi = fmaf(fr, lv.y, lv.x);

    float acc = w2b + ct + cs + p;
    float u   = acc * acc;
    // tanh(x) ~ x(1 - u/3 + 2u^2/15 - 17u^3/315)
    float Th  = acc * fmaf(u, fmaf(u, fmaf(u, -0.05396825397f, 0.13333333333f),
                                   -0.33333333333f), 1.0f);
    return -Th * Phi * rinv;
}

// ---------------------------------------------------------------------------
// Main kernel: 32x32 pair tile per block, 256 threads, 2x2 micro-tile each.
// Dynamic shared memory.
// ---------------------------------------------------------------------------
// float4 offsets in dynamic smem
#define OFF_SHA 0
#define OFF_SHB (OFF_SHA + 32*33)
#define OFF_SLA (OFF_SHB + 32*33)
#define OFF_SLB (OFF_SLA + 32*5)
#define OFF_SP  (OFF_SLB + 32*5)
#define OFF_SQ  (OFF_SP  + 32*25)
#define OFF_F4_END (OFF_SQ + 32*25)
#define SMEM_BYTES (OFF_F4_END*16 + 192*4)

__global__ __launch_bounds__(256)
void main_kernel(const float* __restrict__ h, const float* __restrict__ hsrc,
                 const float* __restrict__ w2_b, float* __restrict__ out)
{
    extern __shared__ float4 sm4[];
    float4 (*sha)[33] = (float4(*)[33])(sm4 + OFF_SHA);
    float4 (*shb)[33] = (float4(*)[33])(sm4 + OFF_SHB);
    float4 (*sla)[5]  = (float4(*)[5]) (sm4 + OFF_SLA);
    float4 (*slb)[5]  = (float4(*)[5]) (sm4 + OFF_SLB);
    float4 (*sP)[25]  = (float4(*)[25])(sm4 + OFF_SP);
    float4 (*sQ)[25]  = (float4(*)[25])(sm4 + OFF_SQ);
    float* fl   = (float*)(sm4 + OFF_F4_END);
    float* shn  = fl;        float* sgn  = fl + 32;
    float* sln  = fl + 64;   float* slsn = fl + 96;
    float* sct  = fl + 128;  float* scs  = fl + 160;

    int bz  = blockIdx.z;
    int t0  = blockIdx.y * TS;
    int s0  = blockIdx.x * TS;
    int tid = threadIdx.x;
    int rt  = bz * TT + t0;
    int rs  = bz * TT + s0;

    // --- stage tiles ---
    const float4* hv = (const float4*)(h    + (size_t)rt * DD);
    const float4* gv = (const float4*)(hsrc + (size_t)rs * DD);
    #pragma unroll
    for (int i = 0; i < 4; i++) {
        int idx = tid + i * 256;
        int r = idx >> 5, c2 = idx & 31;
        sha[r][c2] = hv[r * 32 + c2];
        shb[r][c2] = gv[r * 32 + c2];
    }
    if (tid < 128) {
        const float4* lv  = (const float4*)(g_l[0] + rt * DLL);
        const float4* lsv = (const float4*)(g_l[1] + rs * DLL);
        int r = tid >> 2, c2 = tid & 3;
        sla[r][c2] = lv[r * 4 + c2];
        slb[r][c2] = lsv[r * 4 + c2];
    }
    {
        const float4* pv = (const float4*)(g_PQ[0] + (size_t)rt * 96);
        const float4* qv = (const float4*)(g_PQ[1] + (size_t)rs * 96);
        #pragma unroll
        for (int i = 0; i < 3; i++) {
            int idx = tid + i * 256;      // < 768
            int r = idx / 24, c2 = idx % 24;
            sP[r][c2] = pv[r * 24 + c2];
            sQ[r][c2] = qv[r * 24 + c2];
        }
    }
    if (tid < TS) {
        shn[tid]  = g_hn[0][rt + tid];
        sgn[tid]  = g_hn[1][rs + tid];
        sln[tid]  = g_ln[0][rt + tid];
        slsn[tid] = g_ln[1][rs + tid];
        sct[tid]  = g_c[0][rt + tid];
        scs[tid]  = g_c[1][rs + tid];
    }
    float w2b = w2_b[0];
    __syncthreads();

    int tx = tid & 15, ty = tid >> 4;

    // --- 128-dim h dot products (2x2 micro-tile) ---
    float d00 = 0.f, d01 = 0.f, d10 = 0.f, d11 = 0.f;
    #pragma unroll 8
    for (int k = 0; k < 32; k++) {
        float4 a0 = sha[ty][k];
        float4 a1 = sha[ty + 16][k];
        float4 b0 = shb[tx][k];
        float4 b1 = shb[tx + 16][k];
        d00 = fmaf(a0.x, b0.x, d00); d00 = fmaf(a0.y, b0.y, d00);
        d00 = fmaf(a0.z, b0.z, d00); d00 = fmaf(a0.w, b0.w, d00);
        d01 = fmaf(a0.x, b1.x, d01); d01 = fmaf(a0.y, b1.y, d01);
        d01 = fmaf(a0.z, b1.z, d01); d01 = fmaf(a0.w, b1.w, d01);
        d10 = fmaf(a1.x, b0.x, d10); d10 = fmaf(a1.y, b0.y, d10);
        d10 = fmaf(a1.z, b0.z, d10); d10 = fmaf(a1.w, b0.w, d10);
        d11 = fmaf(a1.x, b1.x, d11); d11 = fmaf(a1.y, b1.y, d11);
        d11 = fmaf(a1.z, b1.z, d11); d11 = fmaf(a1.w, b1.w, d11);
    }

    // --- 16-dim l dot products ---
    float e00 = 0.f, e01 = 0.f, e10 = 0.f, e11 = 0.f;
    #pragma unroll
    for (int k = 0; k < 4; k++) {
        float4 a0 = sla[ty][k];
        float4 a1 = sla[ty + 16][k];
        float4 b0 = slb[tx][k];
        float4 b1 = slb[tx + 16][k];
        e00 = fmaf(a0.x, b0.x, e00); e00 = fmaf(a0.y, b0.y, e00);
        e00 = fmaf(a0.z, b0.z, e00); e00 = fmaf(a0.w, b0.w, e00);
        e01 = fmaf(a0.x, b1.x, e01); e01 = fmaf(a0.y, b1.y, e01);
        e01 = fmaf(a0.z, b1.z, e01); e01 = fmaf(a0.w, b1.w, e01);
        e10 = fmaf(a1.x, b0.x, e10); e10 = fmaf(a1.y, b0.y, e10);
        e10 = fmaf(a1.z, b0.z, e10); e10 = fmaf(a1.w, b0.w, e10);
        e11 = fmaf(a1.x, b1.x, e11); e11 = fmaf(a1.y, b1.y, e11);
        e11 = fmaf(a1.z, b1.z, e11); e11 = fmaf(a1.w, b1.w, e11);
    }

    // --- 96-dim theta bilinear dot products ---
    float p00 = 0.f, p01 = 0.f, p10 = 0.f, p11 = 0.f;
    #pragma unroll 8
    for (int k = 0; k < 24; k++) {
        float4 a0 = sP[ty][k];
        float4 a1 = sP[ty + 16][k];
        float4 b0 = sQ[tx][k];
        float4 b1 = sQ[tx + 16][k];
        p00 = fmaf(a0.x, b0.x, p00); p00 = fmaf(a0.y, b0.y, p00);
        p00 = fmaf(a0.z, b0.z, p00); p00 = fmaf(a0.w, b0.w, p00);
        p01 = fmaf(a0.x, b1.x, p01); p01 = fmaf(a0.y, b1.y, p01);
        p01 = fmaf(a0.z, b1.z, p01); p01 = fmaf(a0.w, b1.w, p01);
        p10 = fmaf(a1.x, b0.x, p10); p10 = fmaf(a1.y, b0.y, p10);
        p10 = fmaf(a1.z, b0.z, p10); p10 = fmaf(a1.w, b0.w, p10);
        p11 = fmaf(a1.x, b1.x, p11); p11 = fmaf(a1.y, b1.y, p11);
        p11 = fmaf(a1.z, b1.z, p11); p11 = fmaf(a1.w, b1.w, p11);
    }

    float hn0  = shn[ty],  hn1  = shn[ty + 16];
    float gn0  = sgn[tx],  gn1  = sgn[tx + 16];
    float ln0  = sln[ty],  ln1  = sln[ty + 16];
    float lsn0 = slsn[tx], lsn1 = slsn[tx + 16];
    float ct0  = sct[ty],  ct1  = sct[ty + 16];
    float cs0  = scs[tx],  cs1  = scs[tx + 16];

    size_t ob = ((size_t)(bz * TT + t0)) * TT + s0;

    out[ob + (size_t)ty * TT + tx] =
        pair_out(d00, e00, p00, hn0, gn0, ln0, lsn0, ct0, cs0, w2b);
    out[ob + (size_t)ty * TT + tx + 16] =
        pair_out(d01, e01, p01, hn0, gn1, ln0, lsn1, ct0, cs1, w2b);
    out[ob + (size_t)(ty + 16) * TT + tx] =
        pair_out(d10, e10, p10, hn1, gn0, ln1, lsn0, ct1, cs0, w2b);
    out[ob + (size_t)(ty + 16) * TT + tx + 16] =
        pair_out(d11, e11, p11, hn1, gn1, ln1, lsn1, ct1, cs1, w2b);
}

// ---------------------------------------------------------------------------
extern "C" void kernel_launch(void* const* d_in, const int* in_sizes, int n_in,
                              void* d_out, int out_size)
{
    (void)in_sizes; (void)n_in; (void)out_size;
    const float* h       = (const float*)d_in[0];
    const float* hsrc    = (const float*)d_in[1];
    const float* W_l     = (const float*)d_in[2];
    const float* W_theta = (const float*)d_in[3];
    const float* phi1_w  = (const float*)d_in[4];
    const float* phi1_b  = (const float*)d_in[5];
    const float* phi2_w  = (const float*)d_in[6];
    const float* phi2_b  = (const float*)d_in[7];
    const float* wq      = (const float*)d_in[8];
    const float* ws      = (const float*)d_in[9];
    const float* wd      = (const float*)d_in[10];
    const float* b1      = (const float*)d_in[11];
    const float* w2_w    = (const float*)d_in[12];
    const float* w2_b    = (const float*)d_in[13];
    float* out = (float*)d_out;

    cudaFuncSetAttribute(main_kernel,
                         cudaFuncAttributeMaxDynamicSharedMemorySize, SMEM_BYTES);

    lut_kernel<<<8, 256>>>(phi1_w, phi1_b, phi2_w, phi2_b);
    prep_kernel<<<dim3(NROWS, 2), 128>>>(h, hsrc, W_l, W_theta, wq, ws, wd, b1, w2_w);
    main_kernel<<<dim3(TT / TS, TT / TS, BB), 256, SMEM_BYTES>>>(h, hsrc, w2_b, out);
}

// round 3
// speedup vs baseline: 2.7267x; 1.5072x over previous
#include <cuda_runtime.h>
#include <math.h>

// Problem constants
#define BB   8
#define TT   512
#define DD   128
#define DLL  16
#define KK   8
#define HTH  32
#define NROWS (BB*TT)   // 4096
#define EPS2 0.0001f

// gelu Taylor: gelu(x) = 0.5x + C0 x^2 + C1 x^4 (|x| small)
#define C0g  0.3989422804014327f
#define C1g  (-0.06649038006690545f)

// Phi LUT: 2048 entries over dl2 in [0,16), step 1/128
#define LUTN   2048
#define LUTSCL 128.0f

// Block tile 64x64, 256 threads, 4x4 micro-tile
#define BT 64

// Scratch
__device__ __align__(16) float  g_l[2][NROWS*DLL];   // projected l vectors
__device__ __align__(16) float  g_PQ[2][NROWS*HTH];  // theta rank-1 vectors
__device__ float  g_hn[2][NROWS];
__device__ float  g_ln[2][NROWS];
__device__ float  g_c[2][NROWS];
__device__ __align__(8) float2 g_lut[LUTN];

// packed dual fp32 fma (sm_103a FFMA2)
#define FMA2(acc, av, bv) \
    asm("fma.rn.f32x2 %0, %1, %2, %0;" : "+l"(acc) : "l"(av), "l"(bv))

__device__ __forceinline__ float hsum2(unsigned long long v) {
    float lo, hi;
    asm("mov.b64 {%0,%1}, %2;" : "=f"(lo), "=f"(hi) : "l"(v));
    return lo + hi;
}

__device__ __forceinline__ float gelu_exact(float x) {
    return 0.5f * x * (1.0f + erff(x * 0.7071067811865475f));
}

// ---------------------------------------------------------------------------
// prep: per-row precompute (sides 0/1) + Phi LUT build (side 2).
// grid (NROWS, 3), block 128.
// ---------------------------------------------------------------------------
__global__ void prep_kernel(const float* __restrict__ h,
                            const float* __restrict__ hsrc,
                            const float* __restrict__ W_l,
                            const float* __restrict__ W_theta,
                            const float* __restrict__ wq,
                            const float* __restrict__ ws,
                            const float* __restrict__ wd,
                            const float* __restrict__ b1,
                            const float* __restrict__ w2_w,
                            const float* __restrict__ phi1_w,
                            const float* __restrict__ phi1_b,
                            const float* __restrict__ phi2_w,
                            const float* __restrict__ phi2_b)
{
    int side = blockIdx.y;
    int tid  = threadIdx.x;

    if (side == 2) {
        // ---- LUT build: 512 blocks x 4 warps = 2048 entries ----
        if (blockIdx.x >= LUTN / 4) return;
        int wid = tid >> 5, lane = tid & 31;
        int e   = blockIdx.x * 4 + wid;
        float w = phi1_w[lane], b = phi1_b[lane], v = phi2_w[lane];
        float x0 = (float)e       * (1.0f / LUTSCL);
        float x1 = (float)(e + 1) * (1.0f / LUTSCL);
        float s0 = gelu_exact(fmaf(x0, w, b)) * v;
        float s1 = gelu_exact(fmaf(x1, w, b)) * v;
        #pragma unroll
        for (int o = 16; o > 0; o >>= 1) {
            s0 += __shfl_xor_sync(0xffffffffu, s0, o);
            s1 += __shfl_xor_sync(0xffffffffu, s1, o);
        }
        if (lane == 0) {
            float ph2b = phi2_b[0];
            float a0 = s0 + ph2b, a1 = s1 + ph2b;
            float c0 = fmaxf(a0, 0.f) + log1pf(expf(-fabsf(a0)));
            float c1 = fmaxf(a1, 0.f) + log1pf(expf(-fabsf(a1)));
            float p0 = expf(-c0 * x0);
            float p1 = expf(-c1 * x1);
            g_lut[e] = make_float2(p0, p1 - p0);
        }
        return;
    }

    int row = blockIdx.x;
    const float* src = (side == 0) ? h : hsrc;

    __shared__ float rs[DD];
    __shared__ float th[KK];
    __shared__ float lr[DLL];

    rs[tid] = src[(size_t)row * DD + tid];
    __syncthreads();

    if (tid < DLL) {
        float a0 = 0.f, a1 = 0.f, a2 = 0.f, a3 = 0.f;
        #pragma unroll 8
        for (int d = 0; d < DD; d += 4) {
            a0 = fmaf(rs[d    ], W_l[(d    ) * DLL + tid], a0);
            a1 = fmaf(rs[d + 1], W_l[(d + 1) * DLL + tid], a1);
            a2 = fmaf(rs[d + 2], W_l[(d + 2) * DLL + tid], a2);
            a3 = fmaf(rs[d + 3], W_l[(d + 3) * DLL + tid], a3);
        }
        float a = (a0 + a1) + (a2 + a3);
        lr[tid] = a;
        g_l[side][row * DLL + tid] = a;
    } else if (tid < DLL + KK) {
        int j = tid - DLL;
        float a0 = 0.f, a1 = 0.f, a2 = 0.f, a3 = 0.f;
        #pragma unroll 8
        for (int d = 0; d < DD; d += 4) {
            a0 = fmaf(rs[d    ], W_theta[(d    ) * KK + j], a0);
            a1 = fmaf(rs[d + 1], W_theta[(d + 1) * KK + j], a1);
            a2 = fmaf(rs[d + 2], W_theta[(d + 2) * KK + j], a2);
            a3 = fmaf(rs[d + 3], W_theta[(d + 3) * KK + j], a3);
        }
        th[j] = (a0 + a1) + (a2 + a3);
    }
    __syncthreads();

    if (tid < HTH) {
        float x;
        if (side == 0) {
            x = b1[tid];
            #pragma unroll
            for (int k = 0; k < KK; k++)
                x = fmaf(th[k], wq[k * HTH + tid] + wd[k * HTH + tid], x);
        } else {
            x = 0.f;
            #pragma unroll
            for (int k = 0; k < KK; k++)
                x = fmaf(th[k], ws[k * HTH + tid] - wd[k * HTH + tid], x);
        }
        float w2 = w2_w[tid];
        float x2 = x * x;
        // rank-1 theta vectors
        g_PQ[side][(size_t)row * HTH + tid] =
            (side == 0) ? (2.0f * C0g * w2 * x) : x;
        // per-row constant: w2*(0.5x + C0 x^2 + C1 x^4)
        float v = w2 * (fmaf(C1g, x2 * x2, fmaf(C0g, x2, 0.5f * x)));
        #pragma unroll
        for (int o = 16; o > 0; o >>= 1)
            v += __shfl_xor_sync(0xffffffffu, v, o);
        if (tid == 0) g_c[side][row] = v;
    } else if (tid == 32) {
        float a0 = 0.f, a1 = 0.f, a2 = 0.f, a3 = 0.f;
        #pragma unroll 8
        for (int d = 0; d < DD; d += 4) {
            a0 = fmaf(rs[d], rs[d], a0);       a1 = fmaf(rs[d+1], rs[d+1], a1);
            a2 = fmaf(rs[d+2], rs[d+2], a2);   a3 = fmaf(rs[d+3], rs[d+3], a3);
        }
        g_hn[side][row] = (a0 + a1) + (a2 + a3);
    } else if (tid == 33) {
        float a = 0.f;
        #pragma unroll
        for (int j = 0; j < DLL; j++) a = fmaf(lr[j], lr[j], a);
        g_ln[side][row] = a;
    }
}

// ---------------------------------------------------------------------------
// main: 64x64 pair tile, 256 threads, 4x4 micro-tile, packed f32x2 dots.
// ---------------------------------------------------------------------------
// float4-unit offsets in dynamic smem
#define OFF_SHA 0
#define OFF_SHB (OFF_SHA + BT*33)
#define OFF_SLA (OFF_SHB + BT*33)
#define OFF_SLB (OFF_SLA + BT*5)
#define OFF_SP  (OFF_SLB + BT*5)
#define OFF_SQ  (OFF_SP  + BT*9)
#define OFF_F4_END (OFF_SQ + BT*9)
#define SMEM_BYTES (OFF_F4_END*16 + 6*BT*4)

__global__ __launch_bounds__(256, 2)
void main_kernel(const float* __restrict__ h, const float* __restrict__ hsrc,
                 const float* __restrict__ w2_b, float* __restrict__ out)
{
    extern __shared__ float4 sm4[];
    float4 (*sha)[33] = (float4(*)[33])(sm4 + OFF_SHA);
    float4 (*shb)[33] = (float4(*)[33])(sm4 + OFF_SHB);
    float4 (*sla)[5]  = (float4(*)[5]) (sm4 + OFF_SLA);
    float4 (*slb)[5]  = (float4(*)[5]) (sm4 + OFF_SLB);
    float4 (*sP)[9]   = (float4(*)[9]) (sm4 + OFF_SP);
    float4 (*sQ)[9]   = (float4(*)[9]) (sm4 + OFF_SQ);
    float* fl   = (float*)(sm4 + OFF_F4_END);
    float* shn  = fl;            float* sgn  = fl + BT;
    float* sln  = fl + 2*BT;     float* slsn = fl + 3*BT;
    float* sct  = fl + 4*BT;     float* scs  = fl + 5*BT;

    int bz  = blockIdx.z;
    int t0  = blockIdx.y * BT;
    int s0  = blockIdx.x * BT;
    int tid = threadIdx.x;
    int rt  = bz * TT + t0;
    int rs  = bz * TT + s0;

    // --- stage tiles ---
    const float4* hv = (const float4*)(h    + (size_t)rt * DD);
    const float4* gv = (const float4*)(hsrc + (size_t)rs * DD);
    #pragma unroll
    for (int i = 0; i < 8; i++) {
        int idx = tid + i * 256;            // < 2048
        int r = idx >> 5, c = idx & 31;
        sha[r][c] = hv[r * 32 + c];
        shb[r][c] = gv[r * 32 + c];
    }
    {
        const float4* lv  = (const float4*)(g_l[0] + (size_t)rt * DLL);
        const float4* lsv = (const float4*)(g_l[1] + (size_t)rs * DLL);
        int r = tid >> 2, c = tid & 3;      // 256 = 64x4
        sla[r][c] = lv[r * 4 + c];
        slb[r][c] = lsv[r * 4 + c];
    }
    {
        const float4* pv = (const float4*)(g_PQ[0] + (size_t)rt * HTH);
        const float4* qv = (const float4*)(g_PQ[1] + (size_t)rs * HTH);
        #pragma unroll
        for (int i = 0; i < 2; i++) {
            int idx = tid + i * 256;        // < 512 = 64x8
            int r = idx >> 3, c = idx & 7;
            sP[r][c] = pv[r * 8 + c];
            sQ[r][c] = qv[r * 8 + c];
        }
    }
    if (tid < BT) {
        shn[tid]  = g_hn[0][rt + tid];
        sgn[tid]  = g_hn[1][rs + tid];
        sln[tid]  = g_ln[0][rt + tid];
        slsn[tid] = g_ln[1][rs + tid];
        sct[tid]  = g_c[0][rt + tid];
        scs[tid]  = g_c[1][rs + tid];
    }
    float w2b = w2_b[0];
    __syncthreads();

    int tx = tid & 15, ty = tid >> 4;

    unsigned long long acc[16];

    // ---- 16-dim l dots -> Phi via LUT ----
    #pragma unroll
    for (int q = 0; q < 16; q++) acc[q] = 0ull;
    #pragma unroll
    for (int k = 0; k < 4; k++) {
        ulonglong2 a[4], b[4];
        #pragma unroll
        for (int i = 0; i < 4; i++) {
            a[i] = *(const ulonglong2*)&sla[ty + 16*i][k];
            b[i] = *(const ulonglong2*)&slb[tx + 16*i][k];
        }
        #pragma unroll
        for (int i = 0; i < 4; i++)
            #pragma unroll
            for (int j = 0; j < 4; j++) {
                FMA2(acc[i*4+j], a[i].x, b[j].x);
                FMA2(acc[i*4+j], a[i].y, b[j].y);
            }
    }
    float tp[16];
    {
        float lnv[4], lsv[4];
        #pragma unroll
        for (int i = 0; i < 4; i++) { lnv[i] = sln[ty + 16*i]; lsv[i] = slsn[tx + 16*i]; }
        #pragma unroll
        for (int i = 0; i < 4; i++)
            #pragma unroll
            for (int j = 0; j < 4; j++) {
                float e   = hsum2(acc[i*4+j]);
                float dl2 = fmaxf(fmaf(-2.f, e, lnv[i] + lsv[j]), 0.f);
                float t   = fminf(dl2 * LUTSCL, (float)(LUTN - 1));
                int   ix  = (int)t;
                float fr  = t - (float)ix;
                float2 lv = __ldg(&g_lut[ix]);
                tp[i*4+j] = fmaf(fr, lv.y, lv.x);   // Phi
            }
    }

    // ---- 32-dim theta dots -> Theta, fold into tp ----
    #pragma unroll
    for (int q = 0; q < 16; q++) acc[q] = 0ull;
    #pragma unroll 4
    for (int k = 0; k < 8; k++) {
        ulonglong2 a[4], b[4];
        #pragma unroll
        for (int i = 0; i < 4; i++) {
            a[i] = *(const ulonglong2*)&sP[ty + 16*i][k];
            b[i] = *(const ulonglong2*)&sQ[tx + 16*i][k];
        }
        #pragma unroll
        for (int i = 0; i < 4; i++)
            #pragma unroll
            for (int j = 0; j < 4; j++) {
                FMA2(acc[i*4+j], a[i].x, b[j].x);
                FMA2(acc[i*4+j], a[i].y, b[j].y);
            }
    }
    {
        float ctv[4], csv[4];
        #pragma unroll
        for (int i = 0; i < 4; i++) { ctv[i] = sct[ty + 16*i]; csv[i] = scs[tx + 16*i]; }
        #pragma unroll
        for (int i = 0; i < 4; i++)
            #pragma unroll
            for (int j = 0; j < 4; j++) {
                float a = w2b + ctv[i] + csv[j] + hsum2(acc[i*4+j]);
                float u = a * a;
                float Th = a * fmaf(u, fmaf(u, fmaf(u, -0.05396825397f,
                                                    0.13333333333f),
                                            -0.33333333333f), 1.0f);
                tp[i*4+j] *= -Th;     // -Theta*Phi
            }
    }

    // ---- 128-dim h dots -> 1/r, final output ----
    #pragma unroll
    for (int q = 0; q < 16; q++) acc[q] = 0ull;
    #pragma unroll 4
    for (int k = 0; k < 32; k++) {
        ulonglong2 a[4], b[4];
        #pragma unroll
        for (int i = 0; i < 4; i++) {
            a[i] = *(const ulonglong2*)&sha[ty + 16*i][k];
            b[i] = *(const ulonglong2*)&shb[tx + 16*i][k];
        }
        #pragma unroll
        for (int i = 0; i < 4; i++)
            #pragma unroll
            for (int j = 0; j < 4; j++) {
                FMA2(acc[i*4+j], a[i].x, b[j].x);
                FMA2(acc[i*4+j], a[i].y, b[j].y);
            }
    }
    {
        float hnv[4], gnv[4];
        #pragma unroll
        for (int i = 0; i < 4; i++) { hnv[i] = shn[ty + 16*i]; gnv[i] = sgn[tx + 16*i]; }
        size_t ob = ((size_t)(bz * TT + t0)) * TT + s0;
        #pragma unroll
        for (int i = 0; i < 4; i++)
            #pragma unroll
            for (int j = 0; j < 4; j++) {
                float d    = hsum2(acc[i*4+j]);
                float dh2  = fmaxf(fmaf(-2.f, d, hnv[i] + gnv[j]), 0.f) + EPS2;
                float rinv = rsqrtf(dh2);
                out[ob + (size_t)(ty + 16*i) * TT + (tx + 16*j)] = tp[i*4+j] * rinv;
            }
    }
}

// ---------------------------------------------------------------------------
extern "C" void kernel_launch(void* const* d_in, const int* in_sizes, int n_in,
                              void* d_out, int out_size)
{
    (void)in_sizes; (void)n_in; (void)out_size;
    const float* h       = (const float*)d_in[0];
    const float* hsrc    = (const float*)d_in[1];
    const float* W_l     = (const float*)d_in[2];
    const float* W_theta = (const float*)d_in[3];
    const float* phi1_w  = (const float*)d_in[4];
    const float* phi1_b  = (const float*)d_in[5];
    const float* phi2_w  = (const float*)d_in[6];
    const float* phi2_b  = (const float*)d_in[7];
    const float* wq      = (const float*)d_in[8];
    const float* ws      = (const float*)d_in[9];
    const float* wd      = (const float*)d_in[10];
    const float* b1      = (const float*)d_in[11];
    const float* w2_w    = (const float*)d_in[12];
    const float* w2_b    = (const float*)d_in[13];
    float* out = (float*)d_out;

    cudaFuncSetAttribute(main_kernel,
                         cudaFuncAttributeMaxDynamicSharedMemorySize, SMEM_BYTES);

    prep_kernel<<<dim3(NROWS, 3), 128>>>(h, hsrc, W_l, W_theta, wq, ws, wd, b1,
                                         w2_w, phi1_w, phi1_b, phi2_w, phi2_b);
    main_kernel<<<dim3(TT / BT, TT / BT, BB), 256, SMEM_BYTES>>>(h, hsrc, w2_b, out);
}

// round 4
// speedup vs baseline: 3.6796x; 1.3495x over previous
#include <cuda_runtime.h>
#include <math.h>

// Problem constants
#define BB   8
#define TT   512
#define DD   128
#define DLL  16
#define KK   8
#define HTH  32
#define NROWS (BB*TT)   // 4096
#define EPS2 0.0001f

// gelu Taylor: gelu(x) = 0.5x + C0 x^2 + C1 x^4 (|x| small)
#define C0g  0.3989422804014327f
#define C1g  (-0.06649038006690545f)

// Phi LUT: 2048 entries over dl2 in [0,16), step 1/128
#define LUTN   2048
#define LUTSCL 128.0f

// Block tile 64x64, 256 threads, 4x4 micro-tile
#define BT 64

// Scratch
__device__ __align__(16) float  g_l[2][NROWS*DLL];   // projected l vectors
__device__ __align__(16) float  g_PQ[2][NROWS*HTH];  // theta rank-1 vectors
__device__ float  g_hn[2][NROWS];
__device__ float  g_ln[2][NROWS];
__device__ float  g_c[2][NROWS];
__device__ __align__(8) float2 g_lut[LUTN];

// packed dual fp32 fma (sm_103a FFMA2)
#define FMA2(acc, av, bv) \
    asm("fma.rn.f32x2 %0, %1, %2, %0;" : "+l"(acc) : "l"(av), "l"(bv))

__device__ __forceinline__ float hsum2(unsigned long long v) {
    float lo, hi;
    asm("mov.b64 {%0,%1}, %2;" : "=f"(lo), "=f"(hi) : "l"(v));
    return lo + hi;
}

__device__ __forceinline__ float gelu_exact(float x) {
    return 0.5f * x * (1.0f + erff(x * 0.7071067811865475f));
}

// ---------------------------------------------------------------------------
// prep: grid (128, 3), block 256.
//   side 0/1: 32 rows per block, staged GEMM-style
//   side 2  : Phi LUT build (16 entries per block, 2 per warp)
// ---------------------------------------------------------------------------
__global__ __launch_bounds__(256)
void prep_kernel(const float* __restrict__ h,
                 const float* __restrict__ hsrc,
                 const float* __restrict__ W_l,
                 const float* __restrict__ W_theta,
                 const float* __restrict__ wq,
                 const float* __restrict__ ws,
                 const float* __restrict__ wd,
                 const float* __restrict__ b1,
                 const float* __restrict__ w2_w,
                 const float* __restrict__ phi1_w,
                 const float* __restrict__ phi1_b,
                 const float* __restrict__ phi2_w,
                 const float* __restrict__ phi2_b)
{
    int side = blockIdx.y;
    int tid  = threadIdx.x;

    if (side == 2) {
        // ---- LUT: 128 blocks x 8 warps x 2 entries = 2048 ----
        int wid = tid >> 5, lane = tid & 31;
        float w = phi1_w[lane], b = phi1_b[lane], v = phi2_w[lane];
        float ph2b = phi2_b[0];
        #pragma unroll
        for (int sub = 0; sub < 2; sub++) {
            int e = blockIdx.x * 16 + wid * 2 + sub;
            float x0 = (float)e       * (1.0f / LUTSCL);
            float x1 = (float)(e + 1) * (1.0f / LUTSCL);
            float s0 = gelu_exact(fmaf(x0, w, b)) * v;
            float s1 = gelu_exact(fmaf(x1, w, b)) * v;
            #pragma unroll
            for (int o = 16; o > 0; o >>= 1) {
                s0 += __shfl_xor_sync(0xffffffffu, s0, o);
                s1 += __shfl_xor_sync(0xffffffffu, s1, o);
            }
            if (lane == 0) {
                float a0 = s0 + ph2b, a1 = s1 + ph2b;
                float c0 = fmaxf(a0, 0.f) + log1pf(expf(-fabsf(a0)));
                float c1 = fmaxf(a1, 0.f) + log1pf(expf(-fabsf(a1)));
                float p0 = expf(-c0 * x0);
                float p1 = expf(-c1 * x1);
                g_lut[e] = make_float2(p0, p1 - p0);
            }
        }
        return;
    }

    int r0 = blockIdx.x * 32;               // 32 rows per block
    const float* src = (side == 0) ? h : hsrc;

    __shared__ float srow[32][132];         // padded: bank = (4r + d) % 32
    __shared__ float sWl[DD * DLL];         // [d][16]
    __shared__ float sWth[DD * KK];         // [d][8]
    __shared__ float sl[32][20];            // l copies for ln
    __shared__ float sth[32][9];            // theta projections
    __shared__ float scw[KK * HTH];         // combined theta weights [k][32]

    // ---- stage ----
    {
        const float4* sv = (const float4*)(src + (size_t)r0 * DD);
        #pragma unroll
        for (int i = 0; i < 4; i++) {
            int idx = tid + i * 256;        // < 1024 f4
            int r = idx >> 5, c = idx & 31;
            *(float4*)&srow[r][c * 4] = sv[r * 32 + c];
        }
        #pragma unroll
        for (int i = 0; i < 8; i++) sWl[tid + i * 256] = W_l[tid + i * 256];
        #pragma unroll
        for (int i = 0; i < 4; i++) sWth[tid + i * 256] = W_theta[tid + i * 256];
        // combined theta weight
        float a = wq[tid], s = ws[tid], d = wd[tid];
        scw[tid] = (side == 0) ? (a + d) : (s - d);
    }
    __syncthreads();

    // ---- Phase A: l = rows @ W_l (512 outputs, 2 per thread) ----
    #pragma unroll
    for (int it = 0; it < 2; it++) {
        int idx = tid + it * 256;
        int r = idx >> 4, c = idx & 15;
        float a0 = 0.f, a1 = 0.f, a2 = 0.f, a3 = 0.f;
        #pragma unroll 8
        for (int d = 0; d < DD; d += 4) {
            a0 = fmaf(srow[r][d    ], sWl[(d    ) * DLL + c], a0);
            a1 = fmaf(srow[r][d + 1], sWl[(d + 1) * DLL + c], a1);
            a2 = fmaf(srow[r][d + 2], sWl[(d + 2) * DLL + c], a2);
            a3 = fmaf(srow[r][d + 3], sWl[(d + 3) * DLL + c], a3);
        }
        float a = (a0 + a1) + (a2 + a3);
        sl[r][c] = a;
        g_l[side][(size_t)(r0 + r) * DLL + c] = a;
    }

    // ---- Phase B: th = rows @ W_theta (256 outputs, 1 per thread) ----
    {
        int r = tid >> 3, c = tid & 7;
        float a0 = 0.f, a1 = 0.f, a2 = 0.f, a3 = 0.f;
        #pragma unroll 8
        for (int d = 0; d < DD; d += 4) {
            a0 = fmaf(srow[r][d    ], sWth[(d    ) * KK + c], a0);
            a1 = fmaf(srow[r][d + 1], sWth[(d + 1) * KK + c], a1);
            a2 = fmaf(srow[r][d + 2], sWth[(d + 2) * KK + c], a2);
            a3 = fmaf(srow[r][d + 3], sWth[(d + 3) * KK + c], a3);
        }
        sth[r][c] = (a0 + a1) + (a2 + a3);
    }

    // ---- hn: 8 threads per row, 16 elems each ----
    {
        int r = tid >> 3, seg = tid & 7;
        float a = 0.f;
        #pragma unroll
        for (int d = 0; d < 16; d++) {
            float x = srow[r][seg * 16 + d];
            a = fmaf(x, x, a);
        }
        a += __shfl_xor_sync(0xffffffffu, a, 1);
        a += __shfl_xor_sync(0xffffffffu, a, 2);
        a += __shfl_xor_sync(0xffffffffu, a, 4);
        if (seg == 0) g_hn[side][r0 + r] = a;
    }
    __syncthreads();

    // ---- ln: 8 threads per row, 2 elems each ----
    {
        int r = tid >> 3, seg = tid & 7;
        float x0 = sl[r][seg * 2], x1 = sl[r][seg * 2 + 1];
        float a = fmaf(x0, x0, x1 * x1);
        a += __shfl_xor_sync(0xffffffffu, a, 1);
        a += __shfl_xor_sync(0xffffffffu, a, 2);
        a += __shfl_xor_sync(0xffffffffu, a, 4);
        if (seg == 0) g_ln[side][r0 + r] = a;
    }

    // ---- PQ + c: 1024 outputs, 4 iters; warp = one row's 32 cols ----
    #pragma unroll
    for (int it = 0; it < 4; it++) {
        int idx = tid + it * 256;
        int r = idx >> 5, c = idx & 31;
        float x = (side == 0) ? b1[c] : 0.f;
        #pragma unroll
        for (int k = 0; k < KK; k++)
            x = fmaf(sth[r][k], scw[k * HTH + c], x);
        float w2 = w2_w[c];
        float x2 = x * x;
        g_PQ[side][(size_t)(r0 + r) * HTH + c] =
            (side == 0) ? (2.0f * C0g * w2 * x) : x;
        float v = w2 * (fmaf(C1g, x2 * x2, fmaf(C0g, x2, 0.5f * x)));
        #pragma unroll
        for (int o = 16; o > 0; o >>= 1)
            v += __shfl_xor_sync(0xffffffffu, v, o);
        if (c == 0) g_c[side][r0 + r] = v;
    }
}

// ---------------------------------------------------------------------------
// main: 64x64 pair tile, 256 threads, 4x4 micro-tile, packed f32x2 dots.
// Lane map 8x4: b-loads = 8 distinct addrs (1 wavefront), a-loads = 4 (1 wf).
// ---------------------------------------------------------------------------
#define OFF_SHA 0
#define OFF_SHB (OFF_SHA + BT*33)
#define OFF_SLA (OFF_SHB + BT*33)
#define OFF_SLB (OFF_SLA + BT*5)
#define OFF_SP  (OFF_SLB + BT*5)
#define OFF_SQ  (OFF_SP  + BT*9)
#define OFF_F4_END (OFF_SQ + BT*9)
#define SMEM_BYTES (OFF_F4_END*16 + 6*BT*4)

__global__ __launch_bounds__(256, 2)
void main_kernel(const float* __restrict__ h, const float* __restrict__ hsrc,
                 const float* __restrict__ w2_b, float* __restrict__ out)
{
    extern __shared__ float4 sm4[];
    float4 (*sha)[33] = (float4(*)[33])(sm4 + OFF_SHA);
    float4 (*shb)[33] = (float4(*)[33])(sm4 + OFF_SHB);
    float4 (*sla)[5]  = (float4(*)[5]) (sm4 + OFF_SLA);
    float4 (*slb)[5]  = (float4(*)[5]) (sm4 + OFF_SLB);
    float4 (*sP)[9]   = (float4(*)[9]) (sm4 + OFF_SP);
    float4 (*sQ)[9]   = (float4(*)[9]) (sm4 + OFF_SQ);
    float* fl   = (float*)(sm4 + OFF_F4_END);
    float* shn  = fl;            float* sgn  = fl + BT;
    float* sln  = fl + 2*BT;     float* slsn = fl + 3*BT;
    float* sct  = fl + 4*BT;     float* scs  = fl + 5*BT;

    int bz  = blockIdx.z;
    int t0  = blockIdx.y * BT;
    int s0  = blockIdx.x * BT;
    int tid = threadIdx.x;
    int rt  = bz * TT + t0;
    int rs  = bz * TT + s0;

    // --- stage tiles ---
    const float4* hv = (const float4*)(h    + (size_t)rt * DD);
    const float4* gv = (const float4*)(hsrc + (size_t)rs * DD);
    #pragma unroll
    for (int i = 0; i < 8; i++) {
        int idx = tid + i * 256;            // < 2048
        int r = idx >> 5, c = idx & 31;
        sha[r][c] = hv[r * 32 + c];
        shb[r][c] = gv[r * 32 + c];
    }
    {
        const float4* lv  = (const float4*)(g_l[0] + (size_t)rt * DLL);
        const float4* lsv = (const float4*)(g_l[1] + (size_t)rs * DLL);
        int r = tid >> 2, c = tid & 3;      // 256 = 64x4
        sla[r][c] = lv[r * 4 + c];
        slb[r][c] = lsv[r * 4 + c];
    }
    {
        const float4* pv = (const float4*)(g_PQ[0] + (size_t)rt * HTH);
        const float4* qv = (const float4*)(g_PQ[1] + (size_t)rs * HTH);
        #pragma unroll
        for (int i = 0; i < 2; i++) {
            int idx = tid + i * 256;        // < 512 = 64x8
            int r = idx >> 3, c = idx & 7;
            sP[r][c] = pv[r * 8 + c];
            sQ[r][c] = qv[r * 8 + c];
        }
    }
    if (tid < BT) {
        shn[tid]  = g_hn[0][rt + tid];
        sgn[tid]  = g_hn[1][rs + tid];
        sln[tid]  = g_ln[0][rt + tid];
        slsn[tid] = g_ln[1][rs + tid];
        sct[tid]  = g_c[0][rt + tid];
        scs[tid]  = g_c[1][rs + tid];
    }
    float w2b = w2_b[0];
    __syncthreads();

    // 8x4 lane map: within warp, 8 distinct cols x 4 distinct rows
    int lane  = tid & 31, w = tid >> 5;
    int rbase = (lane >> 3) + ((w & 3) << 2);   // 0..15
    int cbase = (lane & 7)  + ((w >> 2) << 3);  // 0..15

    unsigned long long acc[16];

    // ---- 16-dim l dots -> Phi via LUT ----
    #pragma unroll
    for (int q = 0; q < 16; q++) acc[q] = 0ull;
    #pragma unroll
    for (int k = 0; k < 4; k++) {
        ulonglong2 a[4], b[4];
        #pragma unroll
        for (int i = 0; i < 4; i++) {
            a[i] = *(const ulonglong2*)&sla[rbase + 16*i][k];
            b[i] = *(const ulonglong2*)&slb[cbase + 16*i][k];
        }
        #pragma unroll
        for (int i = 0; i < 4; i++)
            #pragma unroll
            for (int j = 0; j < 4; j++) {
                FMA2(acc[i*4+j], a[i].x, b[j].x);
                FMA2(acc[i*4+j], a[i].y, b[j].y);
            }
    }
    float tp[16];
    {
        float lnv[4], lsv[4];
        #pragma unroll
        for (int i = 0; i < 4; i++) { lnv[i] = sln[rbase + 16*i]; lsv[i] = slsn[cbase + 16*i]; }
        #pragma unroll
        for (int i = 0; i < 4; i++)
            #pragma unroll
            for (int j = 0; j < 4; j++) {
                float e   = hsum2(acc[i*4+j]);
                float dl2 = fmaxf(fmaf(-2.f, e, lnv[i] + lsv[j]), 0.f);
                float t   = fminf(dl2 * LUTSCL, (float)(LUTN - 1));
                int   ix  = (int)t;
                float fr  = t - (float)ix;
                float2 lv = __ldg(&g_lut[ix]);
                tp[i*4+j] = fmaf(fr, lv.y, lv.x);   // Phi
            }
    }

    // ---- 32-dim theta dots -> Theta, fold into tp ----
    #pragma unroll
    for (int q = 0; q < 16; q++) acc[q] = 0ull;
    #pragma unroll 4
    for (int k = 0; k < 8; k++) {
        ulonglong2 a[4], b[4];
        #pragma unroll
        for (int i = 0; i < 4; i++) {
            a[i] = *(const ulonglong2*)&sP[rbase + 16*i][k];
            b[i] = *(const ulonglong2*)&sQ[cbase + 16*i][k];
        }
        #pragma unroll
        for (int i = 0; i < 4; i++)
            #pragma unroll
            for (int j = 0; j < 4; j++) {
                FMA2(acc[i*4+j], a[i].x, b[j].x);
                FMA2(acc[i*4+j], a[i].y, b[j].y);
            }
    }
    {
        float ctv[4], csv[4];
        #pragma unroll
        for (int i = 0; i < 4; i++) { ctv[i] = sct[rbase + 16*i]; csv[i] = scs[cbase + 16*i]; }
        #pragma unroll
        for (int i = 0; i < 4; i++)
            #pragma unroll
            for (int j = 0; j < 4; j++) {
                float a = w2b + ctv[i] + csv[j] + hsum2(acc[i*4+j]);
                float u = a * a;
                float Th = a * fmaf(u, fmaf(u, fmaf(u, -0.05396825397f,
                                                    0.13333333333f),
                                            -0.33333333333f), 1.0f);
                tp[i*4+j] *= -Th;     // -Theta*Phi
            }
    }

    // ---- 128-dim h dots -> 1/r, final output ----
    #pragma unroll
    for (int q = 0; q < 16; q++) acc[q] = 0ull;
    #pragma unroll 4
    for (int k = 0; k < 32; k++) {
        ulonglong2 a[4], b[4];
        #pragma unroll
        for (int i = 0; i < 4; i++) {
            a[i] = *(const ulonglong2*)&sha[rbase + 16*i][k];
            b[i] = *(const ulonglong2*)&shb[cbase + 16*i][k];
        }
        #pragma unroll
        for (int i = 0; i < 4; i++)
            #pragma unroll
            for (int j = 0; j < 4; j++) {
                FMA2(acc[i*4+j], a[i].x, b[j].x);
                FMA2(acc[i*4+j], a[i].y, b[j].y);
            }
    }
    {
        float hnv[4], gnv[4];
        #pragma unroll
        for (int i = 0; i < 4; i++) { hnv[i] = shn[rbase + 16*i]; gnv[i] = sgn[cbase + 16*i]; }
        size_t ob = ((size_t)(bz * TT + t0)) * TT + s0;
        #pragma unroll
        for (int i = 0; i < 4; i++)
            #pragma unroll
            for (int j = 0; j < 4; j++) {
                float d    = hsum2(acc[i*4+j]);
                float dh2  = fmaxf(fmaf(-2.f, d, hnv[i] + gnv[j]), 0.f) + EPS2;
                float rinv = rsqrtf(dh2);
                out[ob + (size_t)(rbase + 16*i) * TT + (cbase + 16*j)] = tp[i*4+j] * rinv;
            }
    }
}

// ---------------------------------------------------------------------------
extern "C" void kernel_launch(void* const* d_in, const int* in_sizes, int n_in,
                              void* d_out, int out_size)
{
    (void)in_sizes; (void)n_in; (void)out_size;
    const float* h       = (const float*)d_in[0];
    const float* hsrc    = (const float*)d_in[1];
    const float* W_l     = (const float*)d_in[2];
    const float* W_theta = (const float*)d_in[3];
    const float* phi1_w  = (const float*)d_in[4];
    const float* phi1_b  = (const float*)d_in[5];
    const float* phi2_w  = (const float*)d_in[6];
    const float* phi2_b  = (const float*)d_in[7];
    const float* wq      = (const float*)d_in[8];
    const float* ws      = (const float*)d_in[9];
    const float* wd      = (const float*)d_in[10];
    const float* b1      = (const float*)d_in[11];
    const float* w2_w    = (const float*)d_in[12];
    const float* w2_b    = (const float*)d_in[13];
    float* out = (float*)d_out;

    cudaFuncSetAttribute(main_kernel,
                         cudaFuncAttributeMaxDynamicSharedMemorySize, SMEM_BYTES);

    prep_kernel<<<dim3(NROWS/32, 3), 256>>>(h, hsrc, W_l, W_theta, wq, ws, wd, b1,
                                            w2_w, phi1_w, phi1_b, phi2_w, phi2_b);
    main_kernel<<<dim3(TT / BT, TT / BT, BB), 256, SMEM_BYTES>>>(h, hsrc, w2_b, out);
}

// round 6
// speedup vs baseline: 4.1826x; 1.1367x over previous
#include <cuda_runtime.h>
#include <math.h>
#include <stdint.h>

// Problem constants
#define BB   8
#define TT   512
#define DD   128
#define DLL  16
#define KK   8
#define HTH  32
#define NROWS (BB*TT)   // 4096
#define EPS2 0.0001f

// gelu Taylor: gelu(x) = 0.5x + C0 x^2 + C1 x^4 (|x| small)
#define C0g  0.3989422804014327f
#define C1g  (-0.06649038006690545f)

// Phi LUT: 2048 entries over dl2 in [0,16), step 1/128
#define LUTN   2048
#define LUTSCL 128.0f

// Scratch
__device__ __align__(16) float  g_l[2][NROWS*DLL];   // projected l vectors
__device__ __align__(16) float  g_PQ[2][NROWS*HTH];  // theta rank-1 vectors
__device__ float  g_hn[2][NROWS];
__device__ float  g_ln[2][NROWS];
__device__ float  g_c[2][NROWS];
__device__ __align__(16) float2 g_lut[LUTN];

// packed dual fp32 fma (sm_103a FFMA2)
#define FMA2(acc, av, bv) \
    asm("fma.rn.f32x2 %0, %1, %2, %0;" : "+l"(acc) : "l"(av), "l"(bv))

__device__ __forceinline__ float hsum2(unsigned long long v) {
    float lo, hi;
    asm("mov.b64 {%0,%1}, %2;" : "=f"(lo), "=f"(hi) : "l"(v));
    return lo + hi;
}

__device__ __forceinline__ float gelu_exact(float x) {
    return 0.5f * x * (1.0f + erff(x * 0.7071067811865475f));
}

// ---------------------------------------------------------------------------
// prep: grid (64, 3), block 128, dynamic smem.
//   side 0: h rows (t), side 1: hsrc rows (s) — 64 rows per block.
//   side 2: Phi LUT (32 entries per block).
// ---------------------------------------------------------------------------
// float offsets in prep dynamic smem
#define P_SROW 0                       // 64 x 132
#define P_SWT  (P_SROW + 64*132)       // 24 x 132 (transposed weights)
#define P_SL   (P_SWT  + 24*132)       // 64 x 20
#define P_STH  (P_SL   + 64*20)        // 64 x 12
#define P_SCW  (P_STH  + 64*12)        // 8 x 32
#define PREP_SMEM ((P_SCW + 256) * 4)

__global__ __launch_bounds__(128)
void prep_kernel(const float* __restrict__ h,
                 const float* __restrict__ hsrc,
                 const float* __restrict__ W_l,
                 const float* __restrict__ W_theta,
                 const float* __restrict__ wq,
                 const float* __restrict__ ws,
                 const float* __restrict__ wd,
                 const float* __restrict__ b1,
                 const float* __restrict__ w2_w,
                 const float* __restrict__ phi1_w,
                 const float* __restrict__ phi1_b,
                 const float* __restrict__ phi2_w,
                 const float* __restrict__ phi2_b)
{
    int side = blockIdx.y;
    int tid  = threadIdx.x;

    if (side == 2) {
        // ---- LUT: 64 blocks x 4 warps x 8 entries = 2048 ----
        int wid = tid >> 5, lane = tid & 31;
        float w = phi1_w[lane], b = phi1_b[lane], v = phi2_w[lane];
        float ph2b = phi2_b[0];
        #pragma unroll
        for (int sub = 0; sub < 8; sub++) {
            int e = blockIdx.x * 32 + wid * 8 + sub;
            float x0 = (float)e       * (1.0f / LUTSCL);
            float x1 = (float)(e + 1) * (1.0f / LUTSCL);
            float s0 = gelu_exact(fmaf(x0, w, b)) * v;
            float s1 = gelu_exact(fmaf(x1, w, b)) * v;
            #pragma unroll
            for (int o = 16; o > 0; o >>= 1) {
                s0 += __shfl_xor_sync(0xffffffffu, s0, o);
                s1 += __shfl_xor_sync(0xffffffffu, s1, o);
            }
            if (lane == 0) {
                float a0 = s0 + ph2b, a1 = s1 + ph2b;
                float c0 = fmaxf(a0, 0.f) + log1pf(expf(-fabsf(a0)));
                float c1 = fmaxf(a1, 0.f) + log1pf(expf(-fabsf(a1)));
                float p0 = expf(-c0 * x0);
                float p1 = expf(-c1 * x1);
                g_lut[e] = make_float2(p0, p1 - p0);
            }
        }
        return;
    }

    extern __shared__ float ps[];
    float* SROW = ps + P_SROW;
    float* SWT  = ps + P_SWT;
    float* SL   = ps + P_SL;
    float* STH  = ps + P_STH;
    float* SCW  = ps + P_SCW;

    int r0 = blockIdx.x * 64;
    const float* src = (side == 0) ? h : hsrc;

    // ---- stage ----
    {
        const float4* sv = (const float4*)(src + (size_t)r0 * DD);
        #pragma unroll
        for (int i = 0; i < 16; i++) {
            int idx = tid + i * 128;        // < 2048 f4
            int r = idx >> 5, c4 = idx & 31;
            *(float4*)(SROW + r * 132 + c4 * 4) = sv[r * 32 + c4];
        }
        // W_l transposed: SWT[c][d], c<16
        #pragma unroll
        for (int i = 0; i < 16; i++) {
            int idx = tid + i * 128;        // < 2048
            int c = idx & 15, d = idx >> 4;
            SWT[c * 132 + d] = W_l[d * DLL + c];
        }
        // W_theta transposed: SWT[16+c][d], c<8
        #pragma unroll
        for (int i = 0; i < 8; i++) {
            int idx = tid + i * 128;        // < 1024
            int c = idx & 7, d = idx >> 3;
            SWT[(16 + c) * 132 + d] = W_theta[d * KK + c];
        }
        // combined theta weights [k][32]
        #pragma unroll
        for (int i = 0; i < 2; i++) {
            int idx = tid + i * 128;
            float a = wq[idx], s = ws[idx], d = wd[idx];
            SCW[idx] = (side == 0) ? (a + d) : (s - d);
        }
    }
    __syncthreads();

    // ---- register-blocked projection GEMM: 64 rows x 24 cols ----
    // thread: rg = tid>>3 (4 rows), cg = tid&7 (3 cols: cg, cg+8, cg+16)
    {
        int rg = tid >> 3, cg = tid & 7;
        float acc[4][3];
        #pragma unroll
        for (int i = 0; i < 4; i++)
            #pragma unroll
            for (int j = 0; j < 3; j++) acc[i][j] = 0.f;

        const float* sr = SROW + (rg * 4) * 132;
        #pragma unroll 4
        for (int kc = 0; kc < 32; kc++) {
            float4 x[4], w[3];
            #pragma unroll
            for (int i = 0; i < 4; i++)
                x[i] = *(const float4*)(sr + i * 132 + kc * 4);
            #pragma unroll
            for (int j = 0; j < 3; j++)
                w[j] = *(const float4*)(SWT + (cg + 8 * j) * 132 + kc * 4);
            #pragma unroll
            for (int i = 0; i < 4; i++)
                #pragma unroll
                for (int j = 0; j < 3; j++) {
                    acc[i][j] = fmaf(x[i].x, w[j].x, acc[i][j]);
                    acc[i][j] = fmaf(x[i].y, w[j].y, acc[i][j]);
                    acc[i][j] = fmaf(x[i].z, w[j].z, acc[i][j]);
                    acc[i][j] = fmaf(x[i].w, w[j].w, acc[i][j]);
                }
        }
        #pragma unroll
        for (int i = 0; i < 4; i++)
            #pragma unroll
            for (int j = 0; j < 3; j++) {
                int r = rg * 4 + i, c = cg + 8 * j;
                if (c < DLL) {
                    SL[r * 20 + c] = acc[i][j];
                    g_l[side][(size_t)(r0 + r) * DLL + c] = acc[i][j];
                } else {
                    STH[r * 12 + (c - 16)] = acc[i][j];
                }
            }
    }
    __syncthreads();

    // ---- hn: 2 threads per row, 64 elems each ----
    {
        int r = tid >> 1, half = tid & 1;
        const float* sr = SROW + r * 132 + half * 64;
        float a = 0.f;
        #pragma unroll
        for (int c4 = 0; c4 < 16; c4++) {
            float4 x = *(const float4*)(sr + c4 * 4);
            a = fmaf(x.x, x.x, a); a = fmaf(x.y, x.y, a);
            a = fmaf(x.z, x.z, a); a = fmaf(x.w, x.w, a);
        }
        a += __shfl_xor_sync(0xffffffffu, a, 1);
        if (half == 0) g_hn[side][r0 + r] = a;
    }
    // ---- ln: 1 thread per row ----
    if (tid < 64) {
        const float* sr = SL + tid * 20;
        float a = 0.f;
        #pragma unroll
        for (int c4 = 0; c4 < 4; c4++) {
            float4 x = *(const float4*)(sr + c4 * 4);
            a = fmaf(x.x, x.x, a); a = fmaf(x.y, x.y, a);
            a = fmaf(x.z, x.z, a); a = fmaf(x.w, x.w, a);
        }
        g_ln[side][r0 + tid] = a;
    }

    // ---- PQ + c: 64 rows x 32 cols, warp = one row per iter-chunk ----
    #pragma unroll
    for (int i = 0; i < 16; i++) {
        int idx = tid + i * 128;
        int r = idx >> 5, c = idx & 31;
        float x = (side == 0) ? __ldg(&b1[c]) : 0.f;
        #pragma unroll
        for (int k = 0; k < KK; k++)
            x = fmaf(STH[r * 12 + k], SCW[k * HTH + c], x);
        float w2 = __ldg(&w2_w[c]);
        float x2 = x * x;
        g_PQ[side][(size_t)(r0 + r) * HTH + c] =
            (side == 0) ? (2.0f * C0g * w2 * x) : x;
        float v = w2 * (fmaf(C1g, x2 * x2, fmaf(C0g, x2, 0.5f * x)));
        #pragma unroll
        for (int o = 16; o > 0; o >>= 1)
            v += __shfl_xor_sync(0xffffffffu, v, o);
        if (c == 0) g_c[side][r0 + r] = v;
    }
}

// ---------------------------------------------------------------------------
// main: 128x128 pair tile, 256 threads, 8x8 micro-tile, packed f32x2 dots.
// t rows = i-dim (ty + 16i), s rows = j-dim (tx + 16j); out row t, col s.
// ---------------------------------------------------------------------------
// float4 offsets in dynamic smem
#define OFF_SHS 0                      // hsrc (s) 128 x 33 f4
#define OFF_SHT (OFF_SHS + 128*33)     // h (t)
#define OFF_SLS (OFF_SHT + 128*33)     // l s-side 128 x 5 f4
#define OFF_SLT (OFF_SLS + 128*5)
#define OFF_SQS (OFF_SLT + 128*5)      // Q (s) 128 x 9 f4
#define OFF_SPT (OFF_SQS + 128*9)      // P (t)
#define OFF_F4_END (OFF_SPT + 128*9)
#define SMEM_BYTES (OFF_F4_END*16 + 6*128*4)

__global__ __launch_bounds__(256, 1)
void main_kernel(const float* __restrict__ h, const float* __restrict__ hsrc,
                 const float* __restrict__ w2_b, float* __restrict__ out)
{
    extern __shared__ float4 sm4[];
    const float* Hs = (const float*)(sm4 + OFF_SHS);   // stride 132
    const float* Ht = (const float*)(sm4 + OFF_SHT);
    const float* Ls = (const float*)(sm4 + OFF_SLS);   // stride 20
    const float* Lt = (const float*)(sm4 + OFF_SLT);
    const float* Qs = (const float*)(sm4 + OFF_SQS);   // stride 36
    const float* Pt = (const float*)(sm4 + OFF_SPT);
    float* sc = (float*)(sm4 + OFF_F4_END);
    // sc: [0]=hn_t, [128]=hn_s, [256]=ln_t, [384]=ln_s, [512]=c_t, [640]=c_s

    int bz  = blockIdx.z;
    int t0  = blockIdx.y * 128;
    int s0  = blockIdx.x * 128;
    int tid = threadIdx.x;
    int rt  = bz * TT + t0;
    int rs  = bz * TT + s0;

    // --- stage tiles ---
    {
        const float4* tv = (const float4*)(h    + (size_t)rt * DD);
        const float4* sv = (const float4*)(hsrc + (size_t)rs * DD);
        #pragma unroll
        for (int i = 0; i < 16; i++) {
            int idx = tid + i * 256;        // < 4096
            int r = idx >> 5, c4 = idx & 31;
            *(float4*)(Ht + r * 132 + c4 * 4) = tv[r * 32 + c4];
            *(float4*)(Hs + r * 132 + c4 * 4) = sv[r * 32 + c4];
        }
        const float4* lt = (const float4*)(g_l[0] + (size_t)rt * DLL);
        const float4* ls = (const float4*)(g_l[1] + (size_t)rs * DLL);
        #pragma unroll
        for (int i = 0; i < 2; i++) {
            int idx = tid + i * 256;        // < 512
            int r = idx >> 2, c4 = idx & 3;
            *(float4*)(Lt + r * 20 + c4 * 4) = lt[r * 4 + c4];
            *(float4*)(Ls + r * 20 + c4 * 4) = ls[r * 4 + c4];
        }
        const float4* pt = (const float4*)(g_PQ[0] + (size_t)rt * HTH);
        const float4* qs = (const float4*)(g_PQ[1] + (size_t)rs * HTH);
        #pragma unroll
        for (int i = 0; i < 4; i++) {
            int idx = tid + i * 256;        // < 1024
            int r = idx >> 3, c4 = idx & 7;
            *(float4*)(Pt + r * 36 + c4 * 4) = pt[r * 8 + c4];
            *(float4*)(Qs + r * 36 + c4 * 4) = qs[r * 8 + c4];
        }
        if (tid < 128) {
            sc[tid]       = g_hn[0][rt + tid];
            sc[128 + tid] = g_hn[1][rs + tid];
            sc[256 + tid] = g_ln[0][rt + tid];
            sc[384 + tid] = g_ln[1][rs + tid];
            sc[512 + tid] = g_c [0][rt + tid];
            sc[640 + tid] = g_c [1][rs + tid];
        }
    }
    float w2b = __ldg(w2_b);
    __syncthreads();

    int tx = tid & 15, ty = tid >> 4;

    unsigned long long acc[64];
    float tp[64];

    // ================= Phase 1: theta dot (K=32 -> 16 ull) =================
    #pragma unroll
    for (int q = 0; q < 64; q++) acc[q] = 0ull;
    #pragma unroll 4
    for (int k = 0; k < 16; k++) {
        unsigned long long a[8];
        #pragma unroll
        for (int i = 0; i < 8; i++)
            a[i] = *(const unsigned long long*)(Pt + (ty + 16 * i) * 36 + 2 * k);
        #pragma unroll
        for (int j = 0; j < 8; j++) {
            unsigned long long b =
                *(const unsigned long long*)(Qs + (tx + 16 * j) * 36 + 2 * k);
            #pragma unroll
            for (int i = 0; i < 8; i++) FMA2(acc[i * 8 + j], a[i], b);
        }
    }
    #pragma unroll
    for (int i = 0; i < 8; i++) {
        float ct = sc[512 + ty + 16 * i];
        #pragma unroll
        for (int j = 0; j < 8; j++) {
            float a = w2b + ct + sc[640 + tx + 16 * j] + hsum2(acc[i * 8 + j]);
            float u = a * a;
            float Th = a * fmaf(u, fmaf(u, fmaf(u, -0.05396825397f,
                                                0.13333333333f),
                                        -0.33333333333f), 1.0f);
            tp[i * 8 + j] = -Th;
        }
    }

    // ================= Phase 2: l dot (K=16 -> 8 ull) -> Phi ===============
    #pragma unroll
    for (int q = 0; q < 64; q++) acc[q] = 0ull;
    #pragma unroll 4
    for (int k = 0; k < 8; k++) {
        unsigned long long a[8];
        #pragma unroll
        for (int i = 0; i < 8; i++)
            a[i] = *(const unsigned long long*)(Lt + (ty + 16 * i) * 20 + 2 * k);
        #pragma unroll
        for (int j = 0; j < 8; j++) {
            unsigned long long b =
                *(const unsigned long long*)(Ls + (tx + 16 * j) * 20 + 2 * k);
            #pragma unroll
            for (int i = 0; i < 8; i++) FMA2(acc[i * 8 + j], a[i], b);
        }
    }
    #pragma unroll
    for (int i = 0; i < 8; i++) {
        float lnt = sc[256 + ty + 16 * i];
        #pragma unroll
        for (int j = 0; j < 8; j++) {
            float e   = hsum2(acc[i * 8 + j]);
            float dl2 = fmaxf(fmaf(-2.f, e, lnt + sc[384 + tx + 16 * j]), 0.f);
            float t   = fminf(dl2 * LUTSCL, (float)(LUTN - 1));
            int   ix  = (int)t;
            float fr  = t - (float)ix;
            float2 lv = __ldg(&g_lut[ix]);
            tp[i * 8 + j] *= fmaf(fr, lv.y, lv.x);   // *= Phi
        }
    }

    // ================= Phase 3: h dot (K=128 -> 64 ull) -> out =============
    #pragma unroll
    for (int q = 0; q < 64; q++) acc[q] = 0ull;
    #pragma unroll 4
    for (int k = 0; k < 64; k++) {
        unsigned long long a[8];
        #pragma unroll
        for (int i = 0; i < 8; i++)
            a[i] = *(const unsigned long long*)(Ht + (ty + 16 * i) * 132 + 2 * k);
        #pragma unroll
        for (int j = 0; j < 8; j++) {
            unsigned long long b =
                *(const unsigned long long*)(Hs + (tx + 16 * j) * 132 + 2 * k);
            #pragma unroll
            for (int i = 0; i < 8; i++) FMA2(acc[i * 8 + j], a[i], b);
        }
    }
    {
        size_t ob = ((size_t)(bz * TT + t0)) * TT + s0;
        #pragma unroll
        for (int i = 0; i < 8; i++) {
            float hnt = sc[ty + 16 * i];
            size_t orow = ob + (size_t)(ty + 16 * i) * TT;
            #pragma unroll
            for (int j = 0; j < 8; j++) {
                float d    = hsum2(acc[i * 8 + j]);
                float dh2  = fmaxf(fmaf(-2.f, d, hnt + sc[128 + tx + 16 * j]), 0.f)
                             + EPS2;
                out[orow + tx + 16 * j] = tp[i * 8 + j] * rsqrtf(dh2);
            }
        }
    }
}

// ---------------------------------------------------------------------------
extern "C" void kernel_launch(void* const* d_in, const int* in_sizes, int n_in,
                              void* d_out, int out_size)
{
    (void)in_sizes; (void)n_in; (void)out_size;
    const float* h       = (const float*)d_in[0];
    const float* hsrc    = (const float*)d_in[1];
    const float* W_l     = (const float*)d_in[2];
    const float* W_theta = (const float*)d_in[3];
    const float* phi1_w  = (const float*)d_in[4];
    const float* phi1_b  = (const float*)d_in[5];
    const float* phi2_w  = (const float*)d_in[6];
    const float* phi2_b  = (const float*)d_in[7];
    const float* wq      = (const float*)d_in[8];
    const float* ws      = (const float*)d_in[9];
    const float* wd      = (const float*)d_in[10];
    const float* b1      = (const float*)d_in[11];
    const float* w2_w    = (const float*)d_in[12];
    const float* w2_b    = (const float*)d_in[13];
    float* out = (float*)d_out;

    cudaFuncSetAttribute(prep_kernel,
                         cudaFuncAttributeMaxDynamicSharedMemorySize, PREP_SMEM);
    cudaFuncSetAttribute(main_kernel,
                         cudaFuncAttributeMaxDynamicSharedMemorySize, SMEM_BYTES);

    prep_kernel<<<dim3(64, 3), 128, PREP_SMEM>>>(h, hsrc, W_l, W_theta,
                                                 wq, ws, wd, b1, w2_w,
                                                 phi1_w, phi1_b, phi2_w, phi2_b);
    main_kernel<<<dim3(4, 4, BB), 256, SMEM_BYTES>>>(h, hsrc, w2_b, out);
}